// round 1
// baseline (speedup 1.0000x reference)
#include <cuda_runtime.h>
#include <math.h>

#define NS 2048
#define TPB 64

// Per-signal derived quantities (scratch; allocation-free via __device__ globals)
// A: {t, ra, dec, chirp_mass}   B: {f_isco, dist, psi, 0}
__device__ float4 g_pjA[NS];
__device__ float4 g_pjB[NS];

__global__ void precompute_kernel(const float* __restrict__ p) {
    int i = blockIdx.x * blockDim.x + threadIdx.x;
    if (i >= NS) return;
    const float* pi = p + i * 15;
    float p0 = pi[0], p1 = pi[1], p2 = pi[2];
    float ra = pi[3], dec = pi[4], t = pi[5], psi = pi[7];
    float m1 = p0 * 95.0f + 5.0f;
    float m2 = p1 * 95.0f + 5.0f;
    float mc = powf(m1 * m2, 0.6f) / powf(m1 + m2, 0.2f);
    float fisco = 220.0f / (m1 + m2);
    float dist = p2 * 2950.0f + 50.0f;
    g_pjA[i] = make_float4(t, ra, dec, mc);
    g_pjB[i] = make_float4(fisco, dist, psi, 0.0f);
}

__device__ __forceinline__ float gelu_erf(float x) {
    return 0.5f * x * (1.0f + erff(x * 0.70710678118654752f));
}

__global__ __launch_bounds__(TPB)
void cross_signal_kernel(
    const float* __restrict__ iw1, const float* __restrict__ ib1,
    const float* __restrict__ ig1, const float* __restrict__ ibt1,
    const float* __restrict__ iw2, const float* __restrict__ ib2,
    const float* __restrict__ ow1, const float* __restrict__ ob1,
    const float* __restrict__ og1, const float* __restrict__ obt1,
    const float* __restrict__ ow2, const float* __restrict__ ob2,
    float* __restrict__ out)
{
    // iw1 as float4 pairs: s_w4[2*k], s_w4[2*k+1] = iw1[k][0..3], iw1[k][4..7]
    __shared__ float4 s_w4[32];
    // per-k params packed: {ib1[k], ig1[k], ibt1[k], iw2[k]}
    __shared__ float4 s_kp[16];
    __shared__ float s_ow1[256], s_ob1[32], s_og1[32], s_obt1[32];
    __shared__ float s_ow2[512], s_ob2[16];
    __shared__ float s_m[2], s_d[2], s_acc[2][8];
    __shared__ float s_wf[8];   // weighted features
    __shared__ float s_h2[32];

    int tid = threadIdx.x;
    int lane = tid & 31, wid = tid >> 5;

    // cooperative weight staging
    if (tid < 32) {
        const float* w = iw1 + tid * 4;
        s_w4[tid] = make_float4(w[0], w[1], w[2], w[3]);
    }
    if (tid < 16) s_kp[tid] = make_float4(ib1[tid], ig1[tid], ibt1[tid], iw2[tid]);
    for (int k = tid; k < 256; k += TPB) s_ow1[k] = ow1[k];
    if (tid < 32) { s_ob1[tid] = ob1[tid]; s_og1[tid] = og1[tid]; s_obt1[tid] = obt1[tid]; }
    for (int k = tid; k < 512; k += TPB) s_ow2[k] = ow2[k];
    if (tid < 16) s_ob2[tid] = ob2[tid];
    float b2 = ib2[0];
    __syncthreads();

    int i = blockIdx.x;
    float4 aI = g_pjA[i];
    float4 bI = g_pjB[i];

    float m = -INFINITY, d = 0.0f;
    float acc0 = 0.f, acc1 = 0.f, acc2 = 0.f, acc3 = 0.f;
    float acc4 = 0.f, acc5 = 0.f, acc6 = 0.f, acc7 = 0.f;

    for (int j = tid; j < NS; j += TPB) {
        if (j == i) continue;
        float4 aJ = g_pjA[j];
        float4 bJ = g_pjB[j];

        float dt   = fabsf(aI.x - aJ.x);
        float dra  = fabsf(aI.y - aJ.y);
        float ddec = fabsf(aI.z - aJ.z);
        float sky  = sqrtf(dra * dra + ddec * ddec);
        float msim = __fdividef(1.0f, 1.0f + fabsf(aI.w - aJ.w) * (1.0f / 30.0f));
        float fov  = __expf(-fabsf(bI.x - bJ.x) * 0.01f);
        float dmin = fminf(bI.y, bJ.y), dmax = fmaxf(bI.y, bJ.y);
        float drat = __fdividef(dmin, dmax);
        float dpsi = fabsf(bI.z - bJ.z);

        // feature order: dt, sky, msim, fov, drat, dpsi, dra, ddec
        float h[16];
        float s = 0.f, ss = 0.f;
        #pragma unroll
        for (int k = 0; k < 16; k++) {
            float4 wa = s_w4[2 * k];
            float4 wb = s_w4[2 * k + 1];
            float a = s_kp[k].x;
            a = fmaf(wa.x, dt,   a);
            a = fmaf(wa.y, sky,  a);
            a = fmaf(wa.z, msim, a);
            a = fmaf(wa.w, fov,  a);
            a = fmaf(wb.x, drat, a);
            a = fmaf(wb.y, dpsi, a);
            a = fmaf(wb.z, dra,  a);
            a = fmaf(wb.w, ddec, a);
            h[k] = a;
            s += a;
            ss = fmaf(a, a, ss);
        }
        float mu  = s * 0.0625f;
        float var = fmaf(ss, 0.0625f, -mu * mu);
        float inv = rsqrtf(var + 1e-5f);

        float logit = b2;
        #pragma unroll
        for (int k = 0; k < 16; k++) {
            float4 kp = s_kp[k];
            float xn = fmaf((h[k] - mu) * inv, kp.y, kp.z);
            logit = fmaf(kp.w, gelu_erf(xn), logit);
        }

        // online softmax update
        float mn = fmaxf(m, logit);
        float p  = __expf(logit - mn);
        if (mn > m) {
            float c = __expf(m - mn);
            d *= c;
            acc0 *= c; acc1 *= c; acc2 *= c; acc3 *= c;
            acc4 *= c; acc5 *= c; acc6 *= c; acc7 *= c;
            m = mn;
        }
        d += p;
        acc0 = fmaf(p, dt,   acc0);
        acc1 = fmaf(p, sky,  acc1);
        acc2 = fmaf(p, msim, acc2);
        acc3 = fmaf(p, fov,  acc3);
        acc4 = fmaf(p, drat, acc4);
        acc5 = fmaf(p, dpsi, acc5);
        acc6 = fmaf(p, dra,  acc6);
        acc7 = fmaf(p, ddec, acc7);
    }

    // ---- block reduction of (m, d, acc[8]) ----
    unsigned full = 0xffffffffu;
    float M = m;
    #pragma unroll
    for (int o = 16; o; o >>= 1) M = fmaxf(M, __shfl_xor_sync(full, M, o));
    if (lane == 0) s_m[wid] = M;
    __syncthreads();
    M = fmaxf(s_m[0], s_m[1]);

    float c = __expf(m - M);
    d *= c;
    acc0 *= c; acc1 *= c; acc2 *= c; acc3 *= c;
    acc4 *= c; acc5 *= c; acc6 *= c; acc7 *= c;

    #pragma unroll
    for (int o = 16; o; o >>= 1) {
        d    += __shfl_xor_sync(full, d, o);
        acc0 += __shfl_xor_sync(full, acc0, o);
        acc1 += __shfl_xor_sync(full, acc1, o);
        acc2 += __shfl_xor_sync(full, acc2, o);
        acc3 += __shfl_xor_sync(full, acc3, o);
        acc4 += __shfl_xor_sync(full, acc4, o);
        acc5 += __shfl_xor_sync(full, acc5, o);
        acc6 += __shfl_xor_sync(full, acc6, o);
        acc7 += __shfl_xor_sync(full, acc7, o);
    }
    if (lane == 0) {
        s_d[wid] = d;
        s_acc[wid][0] = acc0; s_acc[wid][1] = acc1; s_acc[wid][2] = acc2; s_acc[wid][3] = acc3;
        s_acc[wid][4] = acc4; s_acc[wid][5] = acc5; s_acc[wid][6] = acc6; s_acc[wid][7] = acc7;
    }
    __syncthreads();
    if (tid < 8) {
        float D = s_d[0] + s_d[1];
        s_wf[tid] = __fdividef(s_acc[0][tid] + s_acc[1][tid], D);
    }
    __syncthreads();

    // ---- overlap net: 8 -> 32 (LN + gelu) -> 16 ----
    if (tid < 32) {
        float a = s_ob1[tid];
        #pragma unroll
        for (int f = 0; f < 8; f++) a = fmaf(s_ow1[tid * 8 + f], s_wf[f], a);
        float sv = a, sq = a * a;
        #pragma unroll
        for (int o = 16; o; o >>= 1) {
            sv += __shfl_xor_sync(full, sv, o);
            sq += __shfl_xor_sync(full, sq, o);
        }
        float mu  = sv * (1.0f / 32.0f);
        float var = fmaf(sq, 1.0f / 32.0f, -mu * mu);
        float inv = rsqrtf(var + 1e-5f);
        float xn = fmaf((a - mu) * inv, s_og1[tid], s_obt1[tid]);
        s_h2[tid] = gelu_erf(xn);
    }
    __syncthreads();
    if (tid < 16) {
        float a = s_ob2[tid];
        #pragma unroll
        for (int o = 0; o < 32; o++) a = fmaf(s_ow2[tid * 32 + o], s_h2[o], a);
        out[i * 16 + tid] = a;
    }
}

extern "C" void kernel_launch(void* const* d_in, const int* in_sizes, int n_in,
                              void* d_out, int out_size) {
    const float* params = (const float*)d_in[0];
    const float* iw1  = (const float*)d_in[1];
    const float* ib1  = (const float*)d_in[2];
    const float* ig1  = (const float*)d_in[3];
    const float* ibt1 = (const float*)d_in[4];
    const float* iw2  = (const float*)d_in[5];
    const float* ib2  = (const float*)d_in[6];
    const float* ow1  = (const float*)d_in[7];
    const float* ob1  = (const float*)d_in[8];
    const float* og1  = (const float*)d_in[9];
    const float* obt1 = (const float*)d_in[10];
    const float* ow2  = (const float*)d_in[11];
    const float* ob2  = (const float*)d_in[12];
    float* out = (float*)d_out;

    precompute_kernel<<<(NS + 255) / 256, 256>>>(params);
    cross_signal_kernel<<<NS, TPB>>>(iw1, ib1, ig1, ibt1, iw2, ib2,
                                     ow1, ob1, og1, obt1, ow2, ob2, out);
}

// round 4
// speedup vs baseline: 1.6732x; 1.6732x over previous
#include <cuda_runtime.h>
#include <math.h>

#define NS 2048
#define TILE 64
#define NT (NS / TILE)   // 32

// ---- scratch (allocation-free) ----
__device__ float4 g_pjA[NS];           // {t, ra, dec, chirp_mass}
__device__ float4 g_pjB[NS];           // {f_isco, dist, psi, 0}
__device__ float  g_L[NS * NS];        // pair logits (16.8 MB, L2-resident)

// ---- weights in constant memory (uniform LDCU, zero GPR pressure) ----
__constant__ float4 c_w4[32];          // iw1 [16][8] viewed as 2x float4 per row
__constant__ float  c_ib1[16], c_ig1[16], c_ibt1[16], c_iw2[16], c_ib2[1];
__constant__ float  c_ow1[256], c_ob1[32], c_og1[32], c_obt1[32];
__constant__ float  c_ow2[512], c_ob2[16];

__global__ void precompute_kernel(const float* __restrict__ p) {
    int i = blockIdx.x * blockDim.x + threadIdx.x;
    if (i >= NS) return;
    const float* pi = p + i * 15;
    float m1 = pi[0] * 95.0f + 5.0f;
    float m2 = pi[1] * 95.0f + 5.0f;
    float mc = powf(m1 * m2, 0.6f) / powf(m1 + m2, 0.2f);
    float fisco = 220.0f / (m1 + m2);
    float dist = pi[2] * 2950.0f + 50.0f;
    g_pjA[i] = make_float4(pi[5], pi[3], pi[4], mc);
    g_pjB[i] = make_float4(fisco, dist, pi[7], 0.0f);
}

__device__ __forceinline__ float gelu_erf(float x) {
    return 0.5f * x * (1.0f + erff(x * 0.70710678118654752f));
}

// 8 pairwise features from the per-signal float4s.
__device__ __forceinline__ void pair_features(float4 aI, float4 bI,
                                              float4 aJ, float4 bJ,
                                              float f[8]) {
    float dt   = fabsf(aI.x - aJ.x);
    float dra  = fabsf(aI.y - aJ.y);
    float ddec = fabsf(aI.z - aJ.z);
    float sky  = sqrtf(dra * dra + ddec * ddec);
    float msim = __fdividef(1.0f, 1.0f + fabsf(aI.w - aJ.w) * (1.0f / 30.0f));
    float fov  = __expf(-fabsf(bI.x - bJ.x) * 0.01f);
    float drat = __fdividef(fminf(bI.y, bJ.y), fmaxf(bI.y, bJ.y));
    float dpsi = fabsf(bI.z - bJ.z);
    f[0] = dt;  f[1] = sky;  f[2] = msim; f[3] = fov;
    f[4] = drat; f[5] = dpsi; f[6] = dra; f[7] = ddec;
}

// ---------------- Kernel 1: pair logits, upper triangle only ----------------
__global__ __launch_bounds__(256, 2)
void logits_kernel() {
    int ti = blockIdx.x, tj = blockIdx.y;
    if (tj < ti) return;
    bool diag = (ti == tj);

    __shared__ float4 sAi[TILE], sBi[TILE], sAj[TILE], sBj[TILE];
    int tid = threadIdx.x;
    if (tid < TILE)            sAi[tid]            = g_pjA[ti * TILE + tid];
    else if (tid < 2 * TILE)   sBi[tid - TILE]     = g_pjB[ti * TILE + tid - TILE];
    else if (tid < 3 * TILE)   sAj[tid - 2 * TILE] = g_pjA[tj * TILE + tid - 2 * TILE];
    else                       sBj[tid - 3 * TILE] = g_pjB[tj * TILE + tid - 3 * TILE];
    __syncthreads();

    float b2 = c_ib2[0];
    for (int t = tid; t < TILE * TILE; t += 256) {
        int li = t >> 6, lj = t & (TILE - 1);
        if (diag && li >= lj) continue;

        float f[8];
        pair_features(sAi[li], sBi[li], sAj[lj], sBj[lj], f);

        float h[16];
        float s = 0.f, ss = 0.f;
        #pragma unroll
        for (int k = 0; k < 16; k++) {
            float4 wa = c_w4[2 * k];
            float4 wb = c_w4[2 * k + 1];
            float a = c_ib1[k];
            a = fmaf(wa.x, f[0], a);
            a = fmaf(wa.y, f[1], a);
            a = fmaf(wa.z, f[2], a);
            a = fmaf(wa.w, f[3], a);
            a = fmaf(wb.x, f[4], a);
            a = fmaf(wb.y, f[5], a);
            a = fmaf(wb.z, f[6], a);
            a = fmaf(wb.w, f[7], a);
            h[k] = a;
            s += a;
            ss = fmaf(a, a, ss);
        }
        float mu  = s * 0.0625f;
        float var = fmaf(ss, 0.0625f, -mu * mu);
        float inv = rsqrtf(var + 1e-5f);

        float logit = b2;
        #pragma unroll
        for (int k = 0; k < 16; k++) {
            float xn = fmaf((h[k] - mu) * inv, c_ig1[k], c_ibt1[k]);
            logit = fmaf(c_iw2[k], gelu_erf(xn), logit);
        }

        int i = ti * TILE + li, j = tj * TILE + lj;
        g_L[i * NS + j] = logit;
        g_L[j * NS + i] = logit;
    }
}

// ------- Kernel 2: row softmax + weighted features + overlap net -------
__global__ __launch_bounds__(256)
void softmax_kernel(float* __restrict__ out) {
    int i = blockIdx.x;
    int tid = threadIdx.x;
    int lane = tid & 31, wid = tid >> 5;
    unsigned full = 0xffffffffu;

    float4 aI = g_pjA[i], bI = g_pjB[i];

    // logits bounded (|l| <~ 20), so exp without max-subtraction is safe in fp32
    float d = 0.f;
    float a0 = 0.f, a1 = 0.f, a2 = 0.f, a3 = 0.f, a4 = 0.f, a5 = 0.f, a6 = 0.f, a7 = 0.f;
    const float* Lrow = g_L + (size_t)i * NS;
    for (int j = tid; j < NS; j += 256) {
        if (j == i) continue;
        float p = __expf(Lrow[j]);
        float f[8];
        pair_features(aI, bI, g_pjA[j], g_pjB[j], f);
        d += p;
        a0 = fmaf(p, f[0], a0); a1 = fmaf(p, f[1], a1);
        a2 = fmaf(p, f[2], a2); a3 = fmaf(p, f[3], a3);
        a4 = fmaf(p, f[4], a4); a5 = fmaf(p, f[5], a5);
        a6 = fmaf(p, f[6], a6); a7 = fmaf(p, f[7], a7);
    }

    // reduce 9 values across 8 warps
    #pragma unroll
    for (int o = 16; o; o >>= 1) {
        d  += __shfl_xor_sync(full, d, o);
        a0 += __shfl_xor_sync(full, a0, o);
        a1 += __shfl_xor_sync(full, a1, o);
        a2 += __shfl_xor_sync(full, a2, o);
        a3 += __shfl_xor_sync(full, a3, o);
        a4 += __shfl_xor_sync(full, a4, o);
        a5 += __shfl_xor_sync(full, a5, o);
        a6 += __shfl_xor_sync(full, a6, o);
        a7 += __shfl_xor_sync(full, a7, o);
    }
    __shared__ float s_red[8][9];
    if (lane == 0) {
        s_red[wid][0] = a0; s_red[wid][1] = a1; s_red[wid][2] = a2; s_red[wid][3] = a3;
        s_red[wid][4] = a4; s_red[wid][5] = a5; s_red[wid][6] = a6; s_red[wid][7] = a7;
        s_red[wid][8] = d;
    }
    __syncthreads();
    __shared__ float s_fin[9];
    if (tid < 9) {
        float v = 0.f;
        #pragma unroll
        for (int w = 0; w < 8; w++) v += s_red[w][tid];
        s_fin[tid] = v;
    }
    __syncthreads();
    __shared__ float s_wf[8];
    if (tid < 8) s_wf[tid] = __fdividef(s_fin[tid], s_fin[8]);
    __syncthreads();

    // overlap net: 8 -> 32 (LN + gelu) -> 16
    __shared__ float s_h2[32];
    if (tid < 32) {
        float a = c_ob1[tid];
        #pragma unroll
        for (int f = 0; f < 8; f++) a = fmaf(c_ow1[tid * 8 + f], s_wf[f], a);
        float sv = a, sq = a * a;
        #pragma unroll
        for (int o = 16; o; o >>= 1) {
            sv += __shfl_xor_sync(full, sv, o);
            sq += __shfl_xor_sync(full, sq, o);
        }
        float mu  = sv * (1.0f / 32.0f);
        float var = fmaf(sq, 1.0f / 32.0f, -mu * mu);
        float inv = rsqrtf(var + 1e-5f);
        float xn  = fmaf((a - mu) * inv, c_og1[tid], c_obt1[tid]);
        s_h2[tid] = gelu_erf(xn);
    }
    __syncthreads();
    if (tid < 16) {
        float a = c_ob2[tid];
        #pragma unroll
        for (int o = 0; o < 32; o++) a = fmaf(c_ow2[tid * 32 + o], s_h2[o], a);
        out[i * 16 + tid] = a;
    }
}

extern "C" void kernel_launch(void* const* d_in, const int* in_sizes, int n_in,
                              void* d_out, int out_size) {
    const float* params = (const float*)d_in[0];
    float* out = (float*)d_out;

    // stage weights into constant memory (D2D async copies: graph-capturable)
    cudaMemcpyToSymbolAsync(c_w4,   d_in[1],  16 * 8 * sizeof(float), 0, cudaMemcpyDeviceToDevice);
    cudaMemcpyToSymbolAsync(c_ib1,  d_in[2],  16 * sizeof(float),     0, cudaMemcpyDeviceToDevice);
    cudaMemcpyToSymbolAsync(c_ig1,  d_in[3],  16 * sizeof(float),     0, cudaMemcpyDeviceToDevice);
    cudaMemcpyToSymbolAsync(c_ibt1, d_in[4],  16 * sizeof(float),     0, cudaMemcpyDeviceToDevice);
    cudaMemcpyToSymbolAsync(c_iw2,  d_in[5],  16 * sizeof(float),     0, cudaMemcpyDeviceToDevice);
    cudaMemcpyToSymbolAsync(c_ib2,  d_in[6],  1 * sizeof(float),      0, cudaMemcpyDeviceToDevice);
    cudaMemcpyToSymbolAsync(c_ow1,  d_in[7],  256 * sizeof(float),    0, cudaMemcpyDeviceToDevice);
    cudaMemcpyToSymbolAsync(c_ob1,  d_in[8],  32 * sizeof(float),     0, cudaMemcpyDeviceToDevice);
    cudaMemcpyToSymbolAsync(c_og1,  d_in[9],  32 * sizeof(float),     0, cudaMemcpyDeviceToDevice);
    cudaMemcpyToSymbolAsync(c_obt1, d_in[10], 32 * sizeof(float),     0, cudaMemcpyDeviceToDevice);
    cudaMemcpyToSymbolAsync(c_ow2,  d_in[11], 512 * sizeof(float),    0, cudaMemcpyDeviceToDevice);
    cudaMemcpyToSymbolAsync(c_ob2,  d_in[12], 16 * sizeof(float),     0, cudaMemcpyDeviceToDevice);

    precompute_kernel<<<(NS + 255) / 256, 256>>>(params);
    logits_kernel<<<dim3(NT, NT), 256>>>();
    softmax_kernel<<<NS, 256>>>(out);
}

// round 8
// speedup vs baseline: 1.9858x; 1.1868x over previous
#include <cuda_runtime.h>
#include <math.h>

#define NS 2048
#define TILE 64
#define NT (NS / TILE)            // 32
#define NTRI (NT * (NT + 1) / 2)  // 528

// ---- packed weight layout (concatenated, single constant copy) ----
// [0,128)   iw1            [128,144) ib1      [144,160) ig1
// [160,176) ibt1           [176,192) iw2      [192]     ib2
// [193,449) ow1            [449,481) ob1      [481,513) og1
// [513,545) obt1           [545,1057) ow2     [1057,1073) ob2
#define NPACK 1076
__device__    float g_wpack[NPACK];
__constant__  float c_pack[NPACK];

#define C_W4(q)   (*(const float4*)&c_pack[(q) * 4])   // q in [0,32): iw1 as float4s
#define C_IB1(k)  c_pack[128 + (k)]
#define C_IG1(k)  c_pack[144 + (k)]
#define C_IBT1(k) c_pack[160 + (k)]
#define C_IW2(k)  c_pack[176 + (k)]
#define C_IB2     c_pack[192]
#define C_OW1(t,f) c_pack[193 + (t) * 8 + (f)]
#define C_OB1(t)  c_pack[449 + (t)]
#define C_OG1(t)  c_pack[481 + (t)]
#define C_OBT1(t) c_pack[513 + (t)]
#define C_OW2(t,o) c_pack[545 + (t) * 32 + (o)]
#define C_OB2(t)  c_pack[1057 + (t)]

// ---- scratch ----
__device__ float4 g_pjA[NS];    // {t, ra, dec, chirp_mass}
__device__ float4 g_pjB[NS];    // {f_isco, dist, psi, 0}
__device__ float  g_L[NS * NS]; // pair logits (16.8 MB, L2-resident)

// ---------------- Kernel 0: weight pack + per-signal precompute ----------------
__global__ __launch_bounds__(256)
void setup_kernel(const float* __restrict__ p,
                  const float* __restrict__ iw1, const float* __restrict__ ib1,
                  const float* __restrict__ ig1, const float* __restrict__ ibt1,
                  const float* __restrict__ iw2, const float* __restrict__ ib2,
                  const float* __restrict__ ow1, const float* __restrict__ ob1,
                  const float* __restrict__ og1, const float* __restrict__ obt1,
                  const float* __restrict__ ow2, const float* __restrict__ ob2) {
    int gid = blockIdx.x * blockDim.x + threadIdx.x;

    // weight packing (first 1073 threads, one element each)
    if (gid < 128)        g_wpack[gid] = iw1[gid];
    else if (gid < 144)   g_wpack[gid] = ib1[gid - 128];
    else if (gid < 160)   g_wpack[gid] = ig1[gid - 144];
    else if (gid < 176)   g_wpack[gid] = ibt1[gid - 160];
    else if (gid < 192)   g_wpack[gid] = iw2[gid - 176];
    else if (gid < 193)   g_wpack[gid] = ib2[0];
    else if (gid < 449)   g_wpack[gid] = ow1[gid - 193];
    else if (gid < 481)   g_wpack[gid] = ob1[gid - 449];
    else if (gid < 513)   g_wpack[gid] = og1[gid - 481];
    else if (gid < 545)   g_wpack[gid] = obt1[gid - 513];
    else if (gid < 1057)  g_wpack[gid] = ow2[gid - 545];
    else if (gid < 1073)  g_wpack[gid] = ob2[gid - 1057];

    // per-signal derived quantities
    if (gid < NS) {
        const float* pi = p + gid * 15;
        float m1 = pi[0] * 95.0f + 5.0f;
        float m2 = pi[1] * 95.0f + 5.0f;
        float mc = powf(m1 * m2, 0.6f) / powf(m1 + m2, 0.2f);
        float fisco = 220.0f / (m1 + m2);
        float dist = pi[2] * 2950.0f + 50.0f;
        g_pjA[gid] = make_float4(pi[5], pi[3], pi[4], mc);
        g_pjB[gid] = make_float4(fisco, dist, pi[7], 0.0f);
    }
}

__device__ __forceinline__ float gelu_erf(float x) {
    return 0.5f * x * (1.0f + erff(x * 0.70710678118654752f));
}

__device__ __forceinline__ void pair_features(float4 aI, float4 bI,
                                              float4 aJ, float4 bJ,
                                              float f[8]) {
    float dt   = fabsf(aI.x - aJ.x);
    float dra  = fabsf(aI.y - aJ.y);
    float ddec = fabsf(aI.z - aJ.z);
    float sky  = sqrtf(dra * dra + ddec * ddec);
    float msim = __fdividef(1.0f, 1.0f + fabsf(aI.w - aJ.w) * (1.0f / 30.0f));
    float fov  = __expf(-fabsf(bI.x - bJ.x) * 0.01f);
    float drat = __fdividef(fminf(bI.y, bJ.y), fmaxf(bI.y, bJ.y));
    float dpsi = fabsf(bI.z - bJ.z);
    f[0] = dt;  f[1] = sky;  f[2] = msim; f[3] = fov;
    f[4] = drat; f[5] = dpsi; f[6] = dra; f[7] = ddec;
}

// ---------------- Kernel 1: pair logits, triangular grid ----------------
__global__ __launch_bounds__(256, 3)
void logits_kernel() {
    int b = blockIdx.x;
    // decode (ti, tj), ti <= tj, row-major upper-triangle enumeration
    int ti = (int)((2.0f * NT + 1.0f -
                    sqrtf((2.0f * NT + 1.0f) * (2.0f * NT + 1.0f) - 8.0f * (float)b)) * 0.5f);
    if (ti < 0) ti = 0;
    if (ti > NT - 1) ti = NT - 1;
    while ((ti + 1) * NT - ((ti + 1) * ti) / 2 <= b) ti++;
    while (ti * NT - (ti * (ti - 1)) / 2 > b) ti--;
    int tj = ti + (b - (ti * NT - (ti * (ti - 1)) / 2));
    bool diag = (ti == tj);

    __shared__ float4 sAi[TILE], sBi[TILE], sAj[TILE], sBj[TILE];
    int tid = threadIdx.x;
    if (tid < TILE)            sAi[tid]            = g_pjA[ti * TILE + tid];
    else if (tid < 2 * TILE)   sBi[tid - TILE]     = g_pjB[ti * TILE + tid - TILE];
    else if (tid < 3 * TILE)   sAj[tid - 2 * TILE] = g_pjA[tj * TILE + tid - 2 * TILE];
    else                       sBj[tid - 3 * TILE] = g_pjB[tj * TILE + tid - 3 * TILE];
    __syncthreads();

    float b2 = C_IB2;
    int lj  = tid & (TILE - 1);       // loop-invariant per thread
    int li0 = tid >> 6;
    float4 aJ = sAj[lj];
    float4 bJ = sBj[lj];
    int jcol = tj * TILE + lj;

    for (int li = li0; li < TILE; li += 4) {
        if (diag && li >= lj) continue;

        float f[8];
        pair_features(sAi[li], sBi[li], aJ, bJ, f);

        float h[16];
        float s = 0.f, ss = 0.f;
        #pragma unroll
        for (int k = 0; k < 16; k++) {
            float4 wa = C_W4(2 * k);
            float4 wb = C_W4(2 * k + 1);
            float a = C_IB1(k);
            a = fmaf(wa.x, f[0], a);
            a = fmaf(wa.y, f[1], a);
            a = fmaf(wa.z, f[2], a);
            a = fmaf(wa.w, f[3], a);
            a = fmaf(wb.x, f[4], a);
            a = fmaf(wb.y, f[5], a);
            a = fmaf(wb.z, f[6], a);
            a = fmaf(wb.w, f[7], a);
            h[k] = a;
            s += a;
            ss = fmaf(a, a, ss);
        }
        float mu  = s * 0.0625f;
        float var = fmaf(ss, 0.0625f, -mu * mu);
        float inv = rsqrtf(var + 1e-5f);

        float logit = b2;
        #pragma unroll
        for (int k = 0; k < 16; k++) {
            float xn = fmaf((h[k] - mu) * inv, C_IG1(k), C_IBT1(k));
            logit = fmaf(C_IW2(k), gelu_erf(xn), logit);
        }

        int irow = ti * TILE + li;
        g_L[irow * NS + jcol] = logit;
        g_L[jcol * NS + irow] = logit;
    }
}

// ------- Kernel 2: row softmax + weighted features + overlap net -------
__global__ __launch_bounds__(256)
void softmax_kernel(float* __restrict__ out) {
    int i = blockIdx.x;
    int tid = threadIdx.x;
    int lane = tid & 31, wid = tid >> 5;
    unsigned full = 0xffffffffu;

    float4 aI = g_pjA[i], bI = g_pjB[i];

    float d = 0.f;
    float a0 = 0.f, a1 = 0.f, a2 = 0.f, a3 = 0.f, a4 = 0.f, a5 = 0.f, a6 = 0.f, a7 = 0.f;
    const float* __restrict__ Lrow = g_L + (size_t)i * NS;
    for (int j = tid; j < NS; j += 256) {
        if (j == i) continue;
        float p = __expf(Lrow[j]);
        float f[8];
        pair_features(aI, bI, g_pjA[j], g_pjB[j], f);
        d += p;
        a0 = fmaf(p, f[0], a0); a1 = fmaf(p, f[1], a1);
        a2 = fmaf(p, f[2], a2); a3 = fmaf(p, f[3], a3);
        a4 = fmaf(p, f[4], a4); a5 = fmaf(p, f[5], a5);
        a6 = fmaf(p, f[6], a6); a7 = fmaf(p, f[7], a7);
    }

    #pragma unroll
    for (int o = 16; o; o >>= 1) {
        d  += __shfl_xor_sync(full, d, o);
        a0 += __shfl_xor_sync(full, a0, o);
        a1 += __shfl_xor_sync(full, a1, o);
        a2 += __shfl_xor_sync(full, a2, o);
        a3 += __shfl_xor_sync(full, a3, o);
        a4 += __shfl_xor_sync(full, a4, o);
        a5 += __shfl_xor_sync(full, a5, o);
        a6 += __shfl_xor_sync(full, a6, o);
        a7 += __shfl_xor_sync(full, a7, o);
    }
    __shared__ float s_red[8][9];
    if (lane == 0) {
        s_red[wid][0] = a0; s_red[wid][1] = a1; s_red[wid][2] = a2; s_red[wid][3] = a3;
        s_red[wid][4] = a4; s_red[wid][5] = a5; s_red[wid][6] = a6; s_red[wid][7] = a7;
        s_red[wid][8] = d;
    }
    __syncthreads();
    __shared__ float s_fin[9];
    if (tid < 9) {
        float v = 0.f;
        #pragma unroll
        for (int w = 0; w < 8; w++) v += s_red[w][tid];
        s_fin[tid] = v;
    }
    __syncthreads();
    __shared__ float s_wf[8];
    if (tid < 8) s_wf[tid] = __fdividef(s_fin[tid], s_fin[8]);
    __syncthreads();

    __shared__ float s_h2[32];
    if (tid < 32) {
        float a = C_OB1(tid);
        #pragma unroll
        for (int f = 0; f < 8; f++) a = fmaf(C_OW1(tid, f), s_wf[f], a);
        float sv = a, sq = a * a;
        #pragma unroll
        for (int o = 16; o; o >>= 1) {
            sv += __shfl_xor_sync(full, sv, o);
            sq += __shfl_xor_sync(full, sq, o);
        }
        float mu  = sv * (1.0f / 32.0f);
        float var = fmaf(sq, 1.0f / 32.0f, -mu * mu);
        float inv = rsqrtf(var + 1e-5f);
        float xn  = fmaf((a - mu) * inv, C_OG1(tid), C_OBT1(tid));
        s_h2[tid] = gelu_erf(xn);
    }
    __syncthreads();
    if (tid < 16) {
        float a = C_OB2(tid);
        #pragma unroll
        for (int o = 0; o < 32; o++) a = fmaf(C_OW2(tid, o), s_h2[o], a);
        out[i * 16 + tid] = a;
    }
}

extern "C" void kernel_launch(void* const* d_in, const int* in_sizes, int n_in,
                              void* d_out, int out_size) {
    const float* params = (const float*)d_in[0];
    float* out = (float*)d_out;

    setup_kernel<<<16, 256>>>(params,
        (const float*)d_in[1], (const float*)d_in[2], (const float*)d_in[3],
        (const float*)d_in[4], (const float*)d_in[5], (const float*)d_in[6],
        (const float*)d_in[7], (const float*)d_in[8], (const float*)d_in[9],
        (const float*)d_in[10], (const float*)d_in[11], (const float*)d_in[12]);

    static void* wp = nullptr;
    if (!wp) cudaGetSymbolAddress(&wp, g_wpack);
    cudaMemcpyToSymbolAsync(c_pack, wp, 1073 * sizeof(float), 0, cudaMemcpyDeviceToDevice);

    logits_kernel<<<NTRI, 256>>>();
    softmax_kernel<<<NS, 256>>>(out);
}

// round 9
// speedup vs baseline: 2.0638x; 1.0393x over previous
#include <cuda_runtime.h>
#include <math.h>

#define NS 2048
#define TILE 64
#define NT (NS / TILE)            // 32
#define NTRI (NT * (NT + 1) / 2)  // 528

// ---- packed weight layout (concatenated, single constant copy) ----
#define NPACK 1076
__device__    float g_wpack[NPACK];
__constant__  float c_pack[NPACK];

#define C_W4(q)   (*(const float4*)&c_pack[(q) * 4])   // q in [0,32): iw1 as float4s
#define C_IB1(k)  c_pack[128 + (k)]
#define C_IG1(k)  c_pack[144 + (k)]
#define C_IBT1(k) c_pack[160 + (k)]
#define C_IW2(k)  c_pack[176 + (k)]
#define C_IB2     c_pack[192]
#define C_OW1(t,f) c_pack[193 + (t) * 8 + (f)]
#define C_OB1(t)  c_pack[449 + (t)]
#define C_OG1(t)  c_pack[481 + (t)]
#define C_OBT1(t) c_pack[513 + (t)]
#define C_OW2(t,o) c_pack[545 + (t) * 32 + (o)]
#define C_OB2(t)  c_pack[1057 + (t)]

// ---- scratch ----
__device__ float4 g_pjA[NS];    // {t, ra, dec, chirp_mass}
__device__ float4 g_pjB[NS];    // {f_isco, dist, psi, 0}
__device__ float  g_P[NS * NS]; // exp(logit) per pair; diagonal = 0

// ---------------- Kernel 0: weight pack + per-signal precompute ----------------
__global__ __launch_bounds__(256)
void setup_kernel(const float* __restrict__ p,
                  const float* __restrict__ iw1, const float* __restrict__ ib1,
                  const float* __restrict__ ig1, const float* __restrict__ ibt1,
                  const float* __restrict__ iw2, const float* __restrict__ ib2,
                  const float* __restrict__ ow1, const float* __restrict__ ob1,
                  const float* __restrict__ og1, const float* __restrict__ obt1,
                  const float* __restrict__ ow2, const float* __restrict__ ob2) {
    int gid = blockIdx.x * blockDim.x + threadIdx.x;

    if (gid < 128)        g_wpack[gid] = iw1[gid];
    else if (gid < 144)   g_wpack[gid] = ib1[gid - 128];
    else if (gid < 160)   g_wpack[gid] = ig1[gid - 144];
    else if (gid < 176)   g_wpack[gid] = ibt1[gid - 160];
    else if (gid < 192)   g_wpack[gid] = iw2[gid - 176];
    else if (gid < 193)   g_wpack[gid] = ib2[0];
    else if (gid < 449)   g_wpack[gid] = ow1[gid - 193];
    else if (gid < 481)   g_wpack[gid] = ob1[gid - 449];
    else if (gid < 513)   g_wpack[gid] = og1[gid - 481];
    else if (gid < 545)   g_wpack[gid] = obt1[gid - 513];
    else if (gid < 1057)  g_wpack[gid] = ow2[gid - 545];
    else if (gid < 1073)  g_wpack[gid] = ob2[gid - 1057];

    if (gid < NS) {
        const float* pi = p + gid * 15;
        float m1 = pi[0] * 95.0f + 5.0f;
        float m2 = pi[1] * 95.0f + 5.0f;
        float mc = powf(m1 * m2, 0.6f) / powf(m1 + m2, 0.2f);
        float fisco = 220.0f / (m1 + m2);
        float dist = pi[2] * 2950.0f + 50.0f;
        g_pjA[gid] = make_float4(pi[5], pi[3], pi[4], mc);
        g_pjB[gid] = make_float4(fisco, dist, pi[7], 0.0f);
    }
}

// exact-precision gelu for the cold overlap-net path
__device__ __forceinline__ float gelu_erf(float x) {
    return 0.5f * x * (1.0f + erff(x * 0.70710678118654752f));
}

// fast branch-free gelu via Abramowitz-Stegun 7.1.26 (erf abs err <= 1.5e-7)
__device__ __forceinline__ float gelu_fast(float x) {
    const float a1 =  0.254829592f, a2 = -0.284496736f, a3 = 1.421413741f,
                a4 = -1.453152027f, a5 = 1.061405429f, pp = 0.3275911f;
    float ax = fabsf(x) * 0.70710678118654752f;          // |x|/sqrt(2)
    float t  = __fdividef(1.0f, fmaf(pp, ax, 1.0f));
    float poly = t * fmaf(t, fmaf(t, fmaf(t, fmaf(t, a5, a4), a3), a2), a1);
    float e  = __expf(-ax * ax);
    float er = fmaf(-poly, e, 1.0f);                      // erf(ax), ax>=0
    er = copysignf(er, x);
    return 0.5f * x * (1.0f + er);
}

__device__ __forceinline__ void pair_features(float4 aI, float4 bI,
                                              float4 aJ, float4 bJ,
                                              float f[8]) {
    float dt   = fabsf(aI.x - aJ.x);
    float dra  = fabsf(aI.y - aJ.y);
    float ddec = fabsf(aI.z - aJ.z);
    float sky  = sqrtf(dra * dra + ddec * ddec);
    float msim = __fdividef(1.0f, 1.0f + fabsf(aI.w - aJ.w) * (1.0f / 30.0f));
    float fov  = __expf(-fabsf(bI.x - bJ.x) * 0.01f);
    float drat = __fdividef(fminf(bI.y, bJ.y), fmaxf(bI.y, bJ.y));
    float dpsi = fabsf(bI.z - bJ.z);
    f[0] = dt;  f[1] = sky;  f[2] = msim; f[3] = fov;
    f[4] = drat; f[5] = dpsi; f[6] = dra; f[7] = ddec;
}

// ---------------- Kernel 1: exp(pair logits), triangular grid ----------------
__global__ __launch_bounds__(256, 3)
void logits_kernel() {
    int b = blockIdx.x;
    // decode (ti, tj), ti <= tj
    int ti = (int)((2.0f * NT + 1.0f -
                    sqrtf((2.0f * NT + 1.0f) * (2.0f * NT + 1.0f) - 8.0f * (float)b)) * 0.5f);
    if (ti < 0) ti = 0;
    if (ti > NT - 1) ti = NT - 1;
    while ((ti + 1) * NT - ((ti + 1) * ti) / 2 <= b) ti++;
    while (ti * NT - (ti * (ti - 1)) / 2 > b) ti--;
    int tj = ti + (b - (ti * NT - (ti * (ti - 1)) / 2));
    bool diag = (ti == tj);

    __shared__ float4 sAi[TILE], sBi[TILE], sAj[TILE], sBj[TILE];
    int tid = threadIdx.x;
    if (tid < TILE)            sAi[tid]            = g_pjA[ti * TILE + tid];
    else if (tid < 2 * TILE)   sBi[tid - TILE]     = g_pjB[ti * TILE + tid - TILE];
    else if (tid < 3 * TILE)   sAj[tid - 2 * TILE] = g_pjA[tj * TILE + tid - 2 * TILE];
    else                       sBj[tid - 3 * TILE] = g_pjB[tj * TILE + tid - 3 * TILE];
    __syncthreads();

    float b2 = C_IB2;
    int lj  = tid & (TILE - 1);       // loop-invariant per thread
    int li0 = tid >> 6;
    float4 aJ = sAj[lj];
    float4 bJ = sBj[lj];
    int jcol = tj * TILE + lj;

    for (int li = li0; li < TILE; li += 4) {
        if (diag) {
            if (li == lj) g_P[(ti * TILE + li) * NS + jcol] = 0.0f;  // diagonal
            if (li >= lj) continue;
        }

        float f[8];
        pair_features(sAi[li], sBi[li], aJ, bJ, f);

        float h[16];
        float s = 0.f, ss = 0.f;
        #pragma unroll
        for (int k = 0; k < 16; k++) {
            float4 wa = C_W4(2 * k);
            float4 wb = C_W4(2 * k + 1);
            float a = C_IB1(k);
            a = fmaf(wa.x, f[0], a);
            a = fmaf(wa.y, f[1], a);
            a = fmaf(wa.z, f[2], a);
            a = fmaf(wa.w, f[3], a);
            a = fmaf(wb.x, f[4], a);
            a = fmaf(wb.y, f[5], a);
            a = fmaf(wb.z, f[6], a);
            a = fmaf(wb.w, f[7], a);
            h[k] = a;
            s += a;
            ss = fmaf(a, a, ss);
        }
        float mu  = s * 0.0625f;
        float var = fmaf(ss, 0.0625f, -mu * mu);
        float inv = rsqrtf(var + 1e-5f);

        float logit = b2;
        #pragma unroll
        for (int k = 0; k < 16; k++) {
            float xn = fmaf((h[k] - mu) * inv, C_IG1(k), C_IBT1(k));
            logit = fmaf(C_IW2(k), gelu_fast(xn), logit);
        }

        // |logit| <= ~16 -> exp is fp32-safe without max subtraction
        float pexp = __expf(logit);
        int irow = ti * TILE + li;
        g_P[irow * NS + jcol] = pexp;
        g_P[jcol * NS + irow] = pexp;
    }
}

// ------- Kernel 2: row normalization + weighted features + overlap net -------
__global__ __launch_bounds__(256)
void softmax_kernel(float* __restrict__ out) {
    int i = blockIdx.x;
    int tid = threadIdx.x;
    int lane = tid & 31, wid = tid >> 5;
    unsigned full = 0xffffffffu;

    float4 aI = g_pjA[i], bI = g_pjB[i];

    float d = 0.f;
    float a0 = 0.f, a1 = 0.f, a2 = 0.f, a3 = 0.f, a4 = 0.f, a5 = 0.f, a6 = 0.f, a7 = 0.f;
    const float* __restrict__ Prow = g_P + (size_t)i * NS;
    for (int j = tid; j < NS; j += 256) {
        float p = Prow[j];                 // exp(logit), 0 on diagonal
        float f[8];
        pair_features(aI, bI, g_pjA[j], g_pjB[j], f);
        d += p;
        a0 = fmaf(p, f[0], a0); a1 = fmaf(p, f[1], a1);
        a2 = fmaf(p, f[2], a2); a3 = fmaf(p, f[3], a3);
        a4 = fmaf(p, f[4], a4); a5 = fmaf(p, f[5], a5);
        a6 = fmaf(p, f[6], a6); a7 = fmaf(p, f[7], a7);
    }

    #pragma unroll
    for (int o = 16; o; o >>= 1) {
        d  += __shfl_xor_sync(full, d, o);
        a0 += __shfl_xor_sync(full, a0, o);
        a1 += __shfl_xor_sync(full, a1, o);
        a2 += __shfl_xor_sync(full, a2, o);
        a3 += __shfl_xor_sync(full, a3, o);
        a4 += __shfl_xor_sync(full, a4, o);
        a5 += __shfl_xor_sync(full, a5, o);
        a6 += __shfl_xor_sync(full, a6, o);
        a7 += __shfl_xor_sync(full, a7, o);
    }
    __shared__ float s_red[8][9];
    if (lane == 0) {
        s_red[wid][0] = a0; s_red[wid][1] = a1; s_red[wid][2] = a2; s_red[wid][3] = a3;
        s_red[wid][4] = a4; s_red[wid][5] = a5; s_red[wid][6] = a6; s_red[wid][7] = a7;
        s_red[wid][8] = d;
    }
    __syncthreads();
    __shared__ float s_fin[9];
    if (tid < 9) {
        float v = 0.f;
        #pragma unroll
        for (int w = 0; w < 8; w++) v += s_red[w][tid];
        s_fin[tid] = v;
    }
    __syncthreads();
    __shared__ float s_wf[8];
    if (tid < 8) s_wf[tid] = __fdividef(s_fin[tid], s_fin[8]);
    __syncthreads();

    __shared__ float s_h2[32];
    if (tid < 32) {
        float a = C_OB1(tid);
        #pragma unroll
        for (int f = 0; f < 8; f++) a = fmaf(C_OW1(tid, f), s_wf[f], a);
        float sv = a, sq = a * a;
        #pragma unroll
        for (int o = 16; o; o >>= 1) {
            sv += __shfl_xor_sync(full, sv, o);
            sq += __shfl_xor_sync(full, sq, o);
        }
        float mu  = sv * (1.0f / 32.0f);
        float var = fmaf(sq, 1.0f / 32.0f, -mu * mu);
        float inv = rsqrtf(var + 1e-5f);
        float xn  = fmaf((a - mu) * inv, C_OG1(tid), C_OBT1(tid));
        s_h2[tid] = gelu_erf(xn);
    }
    __syncthreads();
    if (tid < 16) {
        float a = C_OB2(tid);
        #pragma unroll
        for (int o = 0; o < 32; o++) a = fmaf(C_OW2(tid, o), s_h2[o], a);
        out[i * 16 + tid] = a;
    }
}

extern "C" void kernel_launch(void* const* d_in, const int* in_sizes, int n_in,
                              void* d_out, int out_size) {
    const float* params = (const float*)d_in[0];
    float* out = (float*)d_out;

    setup_kernel<<<16, 256>>>(params,
        (const float*)d_in[1], (const float*)d_in[2], (const float*)d_in[3],
        (const float*)d_in[4], (const float*)d_in[5], (const float*)d_in[6],
        (const float*)d_in[7], (const float*)d_in[8], (const float*)d_in[9],
        (const float*)d_in[10], (const float*)d_in[11], (const float*)d_in[12]);

    static void* wp = nullptr;
    if (!wp) cudaGetSymbolAddress(&wp, g_wpack);
    cudaMemcpyToSymbolAsync(c_pack, wp, 1073 * sizeof(float), 0, cudaMemcpyDeviceToDevice);

    logits_kernel<<<NTRI, 256>>>();
    softmax_kernel<<<NS, 256>>>(out);
}

// round 13
// speedup vs baseline: 2.1307x; 1.0324x over previous
#include <cuda_runtime.h>
#include <math.h>

#define NS 2048
#define TILE 64
#define NT (NS / TILE)            // 32
#define NTRI (NT * (NT + 1) / 2)  // 528

typedef unsigned long long u64;

// ---- packed constants: duplicated-pair weights (for f32x2) + scalar rest ----
// rest[] layout (same as before):
// [0,128) iw1  [128,144) ib1  [144,160) ig1  [160,176) ibt1  [176,192) iw2
// [192] ib2    [193,449) ow1  [449,481) ob1  [481,513) og1   [513,545) obt1
// [545,1057) ow2  [1057,1073) ob2
struct CPack {
    ulonglong2 w2[64];    // iw1 dup-pairs: row k at w2[4k..4k+3] = {w0w0,w1w1},{w2w2,w3w3},...
    ulonglong2 kp2[32];   // per k: kp2[2k]={ib1ib1, ig1ig1}, kp2[2k+1]={ibt1ibt1, iw2iw2}
    float rest[1076];
};
__device__   CPack g_all;
__constant__ CPack c_all;

#define C_OW1(t,f) c_all.rest[193 + (t) * 8 + (f)]
#define C_OB1(t)  c_all.rest[449 + (t)]
#define C_OG1(t)  c_all.rest[481 + (t)]
#define C_OBT1(t) c_all.rest[513 + (t)]
#define C_OW2(t,o) c_all.rest[545 + (t) * 32 + (o)]
#define C_OB2(t)  c_all.rest[1057 + (t)]
#define C_IB2     c_all.rest[192]

// ---- scratch ----
__device__ float4 g_pjA[NS];    // {t, ra, dec, chirp_mass}
__device__ float4 g_pjB[NS];    // {f_isco, dist, psi, 0}
__device__ float  g_P[NS * NS]; // exp(logit); diagonal = 0

// ================= f32x2 helpers (sm_103a packed fp32) =================
__device__ __forceinline__ u64 pk2(float lo, float hi) {
    u64 r; asm("mov.b64 %0, {%1, %2};" : "=l"(r) : "f"(lo), "f"(hi)); return r;
}
__device__ __forceinline__ void upk2(u64 v, float& lo, float& hi) {
    asm("mov.b64 {%0, %1}, %2;" : "=f"(lo), "=f"(hi) : "l"(v));
}
__device__ __forceinline__ u64 fma2(u64 a, u64 b, u64 c) {
    u64 d; asm("fma.rn.f32x2 %0, %1, %2, %3;" : "=l"(d) : "l"(a), "l"(b), "l"(c)); return d;
}
__device__ __forceinline__ u64 mul2(u64 a, u64 b) {
    u64 d; asm("mul.rn.f32x2 %0, %1, %2;" : "=l"(d) : "l"(a), "l"(b)); return d;
}
__device__ __forceinline__ u64 add2(u64 a, u64 b) {
    u64 d; asm("add.rn.f32x2 %0, %1, %2;" : "=l"(d) : "l"(a), "l"(b)); return d;
}
__device__ __forceinline__ float frcp(float x) {
    float r; asm("rcp.approx.f32 %0, %1;" : "=f"(r) : "f"(x)); return r;
}
__device__ __forceinline__ float fex2(float x) {
    float r; asm("ex2.approx.f32 %0, %1;" : "=f"(r) : "f"(x)); return r;
}
__device__ __forceinline__ float frsq(float x) {
    float r; asm("rsqrt.approx.f32 %0, %1;" : "=f"(r) : "f"(x)); return r;
}
#define SGN2 0x8000000080000000ull
#define ABS2 0x7FFFFFFF7FFFFFFFull

// ---------------- Kernel 0: weight pack + per-signal precompute ----------------
__device__ __forceinline__ u64 dupf(float w) {
    unsigned b = __float_as_uint(w);
    return ((u64)b << 32) | (u64)b;
}

__global__ __launch_bounds__(256)
void setup_kernel(const float* __restrict__ p,
                  const float* __restrict__ iw1, const float* __restrict__ ib1,
                  const float* __restrict__ ig1, const float* __restrict__ ibt1,
                  const float* __restrict__ iw2, const float* __restrict__ ib2,
                  const float* __restrict__ ow1, const float* __restrict__ ob1,
                  const float* __restrict__ og1, const float* __restrict__ obt1,
                  const float* __restrict__ ow2, const float* __restrict__ ob2) {
    int gid = blockIdx.x * blockDim.x + threadIdx.x;

    // scalar rest[] packing
    if (gid < 128)        g_all.rest[gid] = iw1[gid];
    else if (gid < 144)   g_all.rest[gid] = ib1[gid - 128];
    else if (gid < 160)   g_all.rest[gid] = ig1[gid - 144];
    else if (gid < 176)   g_all.rest[gid] = ibt1[gid - 160];
    else if (gid < 192)   g_all.rest[gid] = iw2[gid - 176];
    else if (gid < 193)   g_all.rest[gid] = ib2[0];
    else if (gid < 449)   g_all.rest[gid] = ow1[gid - 193];
    else if (gid < 481)   g_all.rest[gid] = ob1[gid - 449];
    else if (gid < 513)   g_all.rest[gid] = og1[gid - 481];
    else if (gid < 545)   g_all.rest[gid] = obt1[gid - 513];
    else if (gid < 1057)  g_all.rest[gid] = ow2[gid - 545];
    else if (gid < 1073)  g_all.rest[gid] = ob2[gid - 1057];

    // per-signal derived quantities
    if (gid < NS) {
        const float* pi = p + gid * 15;
        float m1 = pi[0] * 95.0f + 5.0f;
        float m2 = pi[1] * 95.0f + 5.0f;
        float mc = powf(m1 * m2, 0.6f) / powf(m1 + m2, 0.2f);
        float fisco = 220.0f / (m1 + m2);
        float dist = pi[2] * 2950.0f + 50.0f;
        g_pjA[gid] = make_float4(pi[5], pi[3], pi[4], mc);
        g_pjB[gid] = make_float4(fisco, dist, pi[7], 0.0f);
    }

    // duplicated-pair weights for f32x2 path
    if (gid >= 2048 && gid < 2176) {
        int x = gid - 2048;                       // 0..127
        ((u64*)g_all.w2)[x] = dupf(iw1[x]);
    } else if (gid >= 2176 && gid < 2240) {
        int x = gid - 2176;                       // 0..63
        int k = x >> 2, s = x & 3;
        float v = (s == 0) ? ib1[k] : (s == 1) ? ig1[k] : (s == 2) ? ibt1[k] : iw2[k];
        ((u64*)g_all.kp2)[x] = dupf(v);
    }
}

// exact-precision gelu for the cold overlap-net path
__device__ __forceinline__ float gelu_erf(float x) {
    return 0.5f * x * (1.0f + erff(x * 0.70710678118654752f));
}

__device__ __forceinline__ void pair_features(float4 aI, float4 bI,
                                              float4 aJ, float4 bJ,
                                              float f[8]) {
    float dt   = fabsf(aI.x - aJ.x);
    float dra  = fabsf(aI.y - aJ.y);
    float ddec = fabsf(aI.z - aJ.z);
    float sky  = sqrtf(dra * dra + ddec * ddec);
    float msim = __fdividef(1.0f, 1.0f + fabsf(aI.w - aJ.w) * (1.0f / 30.0f));
    float fov  = __expf(-fabsf(bI.x - bJ.x) * 0.01f);
    float drat = __fdividef(fminf(bI.y, bJ.y), fmaxf(bI.y, bJ.y));
    float dpsi = fabsf(bI.z - bJ.z);
    f[0] = dt;  f[1] = sky;  f[2] = msim; f[3] = fov;
    f[4] = drat; f[5] = dpsi; f[6] = dra; f[7] = ddec;
}

// ---------------- Kernel 1: exp(pair logits), f32x2 dual-pair pipeline ----------------
__global__ __launch_bounds__(256, 2)
void logits_kernel() {
    int b = blockIdx.x;
    // decode (ti, tj), ti <= tj
    int ti = (int)((2.0f * NT + 1.0f -
                    sqrtf((2.0f * NT + 1.0f) * (2.0f * NT + 1.0f) - 8.0f * (float)b)) * 0.5f);
    if (ti < 0) ti = 0;
    if (ti > NT - 1) ti = NT - 1;
    while ((ti + 1) * NT - ((ti + 1) * ti) / 2 <= b) ti++;
    while (ti * NT - (ti * (ti - 1)) / 2 > b) ti--;
    int tj = ti + (b - (ti * NT - (ti * (ti - 1)) / 2));
    bool diag = (ti == tj);

    __shared__ float4 sAi[TILE], sBi[TILE], sAj[TILE], sBj[TILE];
    int tid = threadIdx.x;
    if (tid < TILE)            sAi[tid]            = g_pjA[ti * TILE + tid];
    else if (tid < 2 * TILE)   sBi[tid - TILE]     = g_pjB[ti * TILE + tid - TILE];
    else if (tid < 3 * TILE)   sAj[tid - 2 * TILE] = g_pjA[tj * TILE + tid - 2 * TILE];
    else                       sBj[tid - 3 * TILE] = g_pjB[tj * TILE + tid - 3 * TILE];
    __syncthreads();

    int lj  = tid & (TILE - 1);
    int li0 = tid >> 6;            // 0..3
    float4 aJ = sAj[lj];
    float4 bJ = sBj[lj];
    int jcol = tj * TILE + lj;
    int ibase = ti * TILE;

    // hoisted packed constants
    const u64 c_one   = pk2(1.0f, 1.0f);
    const u64 c_half  = pk2(0.5f, 0.5f);
    const u64 c_isq2  = pk2(0.70710678118654752f, 0.70710678118654752f);
    const u64 c_pp    = pk2(0.3275911f, 0.3275911f);
    const u64 c_a1    = pk2(0.254829592f, 0.254829592f);
    const u64 c_a2    = pk2(-0.284496736f, -0.284496736f);
    const u64 c_a3    = pk2(1.421413741f, 1.421413741f);
    const u64 c_a4    = pk2(-1.453152027f, -1.453152027f);
    const u64 c_a5    = pk2(1.061405429f, 1.061405429f);
    const u64 c_nl2e  = pk2(-1.4426950408889634f, -1.4426950408889634f);
    const u64 c_s16   = pk2(0.0625f, 0.0625f);
    const u64 c_eps   = pk2(1e-5f, 1e-5f);
    float b2s = C_IB2;
    const u64 c_b2    = pk2(b2s, b2s);

    // diagonal zeros
    if (diag) {
        g_P[(ibase + lj) * NS + jcol] = 0.0f;
    }

    for (int li = li0; li < 32; li += 4) {
        int la = li, lb = li + 32;   // two independent pairs

        float fa[8], fb[8];
        pair_features(sAi[la], sBi[la], aJ, bJ, fa);
        pair_features(sAi[lb], sBi[lb], aJ, bJ, fb);

        u64 f2[8];
        #pragma unroll
        for (int q = 0; q < 8; q++) f2[q] = pk2(fa[q], fb[q]);

        // 8->16 matvec + moment accumulation, all f32x2
        u64 h2[16];
        u64 s2 = 0, ss2 = 0;   // +0.0 packed == bit pattern 0
        #pragma unroll
        for (int k = 0; k < 16; k++) {
            ulonglong2 p0 = c_all.w2[4 * k];
            ulonglong2 p1 = c_all.w2[4 * k + 1];
            ulonglong2 p2 = c_all.w2[4 * k + 2];
            ulonglong2 p3 = c_all.w2[4 * k + 3];
            u64 a = c_all.kp2[2 * k].x;           // ib1 dup
            a = fma2(p0.x, f2[0], a);
            a = fma2(p0.y, f2[1], a);
            a = fma2(p1.x, f2[2], a);
            a = fma2(p1.y, f2[3], a);
            a = fma2(p2.x, f2[4], a);
            a = fma2(p2.y, f2[5], a);
            a = fma2(p3.x, f2[6], a);
            a = fma2(p3.y, f2[7], a);
            h2[k] = a;
            s2 = add2(s2, a);
            ss2 = fma2(a, a, ss2);
        }

        // LayerNorm moments
        u64 mu2  = mul2(s2, c_s16);
        u64 var2 = fma2(ss2, c_s16, mul2(mu2, mu2) ^ SGN2);
        var2 = add2(var2, c_eps);
        float vlo, vhi; upk2(var2, vlo, vhi);
        u64 inv2 = pk2(frsq(vlo), frsq(vhi));
        u64 negmu2 = mu2 ^ SGN2;

        // gelu(A&S) + logit accumulation
        u64 logit2 = c_b2;
        #pragma unroll
        for (int k = 0; k < 16; k++) {
            ulonglong2 q0 = c_all.kp2[2 * k];       // {ib1, ig1}
            ulonglong2 q1 = c_all.kp2[2 * k + 1];   // {ibt1, iw2}
            u64 t = add2(h2[k], negmu2);
            t = mul2(t, inv2);
            u64 xn = fma2(t, q0.y, q1.x);

            u64 sgn = xn & SGN2;
            u64 ax  = mul2(xn, c_isq2) & ABS2;
            u64 den = fma2(ax, c_pp, c_one);
            float dlo, dhi; upk2(den, dlo, dhi);
            u64 tr = pk2(frcp(dlo), frcp(dhi));
            u64 poly = fma2(tr, c_a5, c_a4);
            poly = fma2(tr, poly, c_a3);
            poly = fma2(tr, poly, c_a2);
            poly = fma2(tr, poly, c_a1);
            poly = mul2(tr, poly);
            u64 mm = mul2(mul2(ax, ax), c_nl2e);
            float mlo, mhi; upk2(mm, mlo, mhi);
            u64 e = pk2(fex2(mlo), fex2(mhi));
            u64 er = fma2(poly ^ SGN2, e, c_one);   // 1 - poly*e  (>= 0)
            er |= sgn;                               // copysign(er, xn)
            u64 hx = mul2(xn, c_half);
            u64 g  = fma2(hx, er, hx);               // 0.5*xn*(1+er)
            logit2 = fma2(g, q1.y, logit2);
        }

        float la_l, lb_l; upk2(logit2, la_l, lb_l);
        float pa = __expf(la_l);
        float pb = __expf(lb_l);

        int ia = ibase + la, ib = ibase + lb;
        if (!diag || la < lj) {
            g_P[ia * NS + jcol] = pa;
            g_P[jcol * NS + ia] = pa;
        }
        if (!diag || lb < lj) {
            g_P[ib * NS + jcol] = pb;
            g_P[jcol * NS + ib] = pb;
        }
    }
}

// ------- Kernel 2: row normalization + weighted features + overlap net -------
__global__ __launch_bounds__(256)
void softmax_kernel(float* __restrict__ out) {
    int i = blockIdx.x;
    int tid = threadIdx.x;
    int lane = tid & 31, wid = tid >> 5;
    unsigned full = 0xffffffffu;

    float4 aI = g_pjA[i], bI = g_pjB[i];

    float d = 0.f;
    float a0 = 0.f, a1 = 0.f, a2 = 0.f, a3 = 0.f, a4 = 0.f, a5 = 0.f, a6 = 0.f, a7 = 0.f;
    const float* __restrict__ Prow = g_P + (size_t)i * NS;
    for (int j = tid; j < NS; j += 256) {
        float p = Prow[j];                 // exp(logit), 0 on diagonal
        float f[8];
        pair_features(aI, bI, g_pjA[j], g_pjB[j], f);
        d += p;
        a0 = fmaf(p, f[0], a0); a1 = fmaf(p, f[1], a1);
        a2 = fmaf(p, f[2], a2); a3 = fmaf(p, f[3], a3);
        a4 = fmaf(p, f[4], a4); a5 = fmaf(p, f[5], a5);
        a6 = fmaf(p, f[6], a6); a7 = fmaf(p, f[7], a7);
    }

    #pragma unroll
    for (int o = 16; o; o >>= 1) {
        d  += __shfl_xor_sync(full, d, o);
        a0 += __shfl_xor_sync(full, a0, o);
        a1 += __shfl_xor_sync(full, a1, o);
        a2 += __shfl_xor_sync(full, a2, o);
        a3 += __shfl_xor_sync(full, a3, o);
        a4 += __shfl_xor_sync(full, a4, o);
        a5 += __shfl_xor_sync(full, a5, o);
        a6 += __shfl_xor_sync(full, a6, o);
        a7 += __shfl_xor_sync(full, a7, o);
    }
    __shared__ float s_red[8][9];
    if (lane == 0) {
        s_red[wid][0] = a0; s_red[wid][1] = a1; s_red[wid][2] = a2; s_red[wid][3] = a3;
        s_red[wid][4] = a4; s_red[wid][5] = a5; s_red[wid][6] = a6; s_red[wid][7] = a7;
        s_red[wid][8] = d;
    }
    __syncthreads();
    __shared__ float s_fin[9];
    if (tid < 9) {
        float v = 0.f;
        #pragma unroll
        for (int w = 0; w < 8; w++) v += s_red[w][tid];
        s_fin[tid] = v;
    }
    __syncthreads();
    __shared__ float s_wf[8];
    if (tid < 8) s_wf[tid] = __fdividef(s_fin[tid], s_fin[8]);
    __syncthreads();

    __shared__ float s_h2[32];
    if (tid < 32) {
        float a = C_OB1(tid);
        #pragma unroll
        for (int f = 0; f < 8; f++) a = fmaf(C_OW1(tid, f), s_wf[f], a);
        float sv = a, sq = a * a;
        #pragma unroll
        for (int o = 16; o; o >>= 1) {
            sv += __shfl_xor_sync(full, sv, o);
            sq += __shfl_xor_sync(full, sq, o);
        }
        float mu  = sv * (1.0f / 32.0f);
        float var = fmaf(sq, 1.0f / 32.0f, -mu * mu);
        float inv = rsqrtf(var + 1e-5f);
        float xn  = fmaf((a - mu) * inv, C_OG1(tid), C_OBT1(tid));
        s_h2[tid] = gelu_erf(xn);
    }
    __syncthreads();
    if (tid < 16) {
        float a = C_OB2(tid);
        #pragma unroll
        for (int o = 0; o < 32; o++) a = fmaf(C_OW2(tid, o), s_h2[o], a);
        out[i * 16 + tid] = a;
    }
}

extern "C" void kernel_launch(void* const* d_in, const int* in_sizes, int n_in,
                              void* d_out, int out_size) {
    const float* params = (const float*)d_in[0];
    float* out = (float*)d_out;

    setup_kernel<<<16, 256>>>(params,
        (const float*)d_in[1], (const float*)d_in[2], (const float*)d_in[3],
        (const float*)d_in[4], (const float*)d_in[5], (const float*)d_in[6],
        (const float*)d_in[7], (const float*)d_in[8], (const float*)d_in[9],
        (const float*)d_in[10], (const float*)d_in[11], (const float*)d_in[12]);

    static void* wp = nullptr;
    if (!wp) cudaGetSymbolAddress(&wp, g_all);
    cudaMemcpyToSymbolAsync(c_all, wp, sizeof(CPack), 0, cudaMemcpyDeviceToDevice);

    logits_kernel<<<NTRI, 256>>>();
    softmax_kernel<<<NS, 256>>>(out);
}

// round 16
// speedup vs baseline: 2.2399x; 1.0513x over previous
#include <cuda_runtime.h>
#include <math.h>

#define NS 2048
#define TILE 64
#define NT (NS / TILE)            // 32
#define NTRI (NT * (NT + 1) / 2)  // 528

typedef unsigned long long u64;

// ---- packed constants ----
// w2: centered iw1 dup-pairs (u64 index = 8k+f)
// kp2 (u64 index = 4k+s): s0 = ib1_k - mean(ib1) (centered bias)
//                         s1 = ig1_k / sqrt(2)
//                         s2 = ibt1_k / sqrt(2)
//                         s3 = iw2_k * (sqrt(2)/2)
// rest[]: original scalar layout (overlap net + ib2)
struct CPack {
    ulonglong2 w2[64];
    ulonglong2 kp2[32];
    float rest[1076];
};
__device__   CPack g_all;
__constant__ CPack c_all;

#define C_OW1(t,f) c_all.rest[193 + (t) * 8 + (f)]
#define C_OB1(t)  c_all.rest[449 + (t)]
#define C_OG1(t)  c_all.rest[481 + (t)]
#define C_OBT1(t) c_all.rest[513 + (t)]
#define C_OW2(t,o) c_all.rest[545 + (t) * 32 + (o)]
#define C_OB2(t)  c_all.rest[1057 + (t)]
#define C_IB2     c_all.rest[192]

// ---- scratch ----
__device__ float4 g_pjA[NS];    // {t, ra, dec, chirp_mass}
__device__ float4 g_pjB[NS];    // {f_isco, dist, psi, 0}
__device__ float  g_P[NS * NS]; // exp(logit); diagonal = 0

// ================= f32x2 helpers =================
__device__ __forceinline__ u64 pk2(float lo, float hi) {
    u64 r; asm("mov.b64 %0, {%1, %2};" : "=l"(r) : "f"(lo), "f"(hi)); return r;
}
__device__ __forceinline__ void upk2(u64 v, float& lo, float& hi) {
    asm("mov.b64 {%0, %1}, %2;" : "=f"(lo), "=f"(hi) : "l"(v));
}
__device__ __forceinline__ u64 fma2(u64 a, u64 b, u64 c) {
    u64 d; asm("fma.rn.f32x2 %0, %1, %2, %3;" : "=l"(d) : "l"(a), "l"(b), "l"(c)); return d;
}
__device__ __forceinline__ u64 mul2(u64 a, u64 b) {
    u64 d; asm("mul.rn.f32x2 %0, %1, %2;" : "=l"(d) : "l"(a), "l"(b)); return d;
}
__device__ __forceinline__ u64 add2(u64 a, u64 b) {
    u64 d; asm("add.rn.f32x2 %0, %1, %2;" : "=l"(d) : "l"(a), "l"(b)); return d;
}
__device__ __forceinline__ float frcp(float x) {
    float r; asm("rcp.approx.f32 %0, %1;" : "=f"(r) : "f"(x)); return r;
}
__device__ __forceinline__ float fex2(float x) {
    float r; asm("ex2.approx.f32 %0, %1;" : "=f"(r) : "f"(x)); return r;
}
__device__ __forceinline__ float frsq(float x) {
    float r; asm("rsqrt.approx.f32 %0, %1;" : "=f"(r) : "f"(x)); return r;
}
#define SGN2 0x8000000080000000ull
#define ABS2 0x7FFFFFFF7FFFFFFFull

__device__ __forceinline__ u64 dupf(float w) {
    unsigned b = __float_as_uint(w);
    return ((u64)b << 32) | (u64)b;
}

// ---------------- Kernel 0: weight pack + per-signal precompute ----------------
__global__ __launch_bounds__(256)
void setup_kernel(const float* __restrict__ p,
                  const float* __restrict__ iw1, const float* __restrict__ ib1,
                  const float* __restrict__ ig1, const float* __restrict__ ibt1,
                  const float* __restrict__ iw2, const float* __restrict__ ib2,
                  const float* __restrict__ ow1, const float* __restrict__ ob1,
                  const float* __restrict__ og1, const float* __restrict__ obt1,
                  const float* __restrict__ ow2, const float* __restrict__ ob2) {
    int gid = blockIdx.x * blockDim.x + threadIdx.x;

    // scalar rest[] packing
    if (gid < 128)        g_all.rest[gid] = iw1[gid];
    else if (gid < 144)   g_all.rest[gid] = ib1[gid - 128];
    else if (gid < 160)   g_all.rest[gid] = ig1[gid - 144];
    else if (gid < 176)   g_all.rest[gid] = ibt1[gid - 160];
    else if (gid < 192)   g_all.rest[gid] = iw2[gid - 176];
    else if (gid < 193)   g_all.rest[gid] = ib2[0];
    else if (gid < 449)   g_all.rest[gid] = ow1[gid - 193];
    else if (gid < 481)   g_all.rest[gid] = ob1[gid - 449];
    else if (gid < 513)   g_all.rest[gid] = og1[gid - 481];
    else if (gid < 545)   g_all.rest[gid] = obt1[gid - 513];
    else if (gid < 1057)  g_all.rest[gid] = ow2[gid - 545];
    else if (gid < 1073)  g_all.rest[gid] = ob2[gid - 1057];

    // per-signal derived quantities
    if (gid < NS) {
        const float* pi = p + gid * 15;
        float m1 = pi[0] * 95.0f + 5.0f;
        float m2 = pi[1] * 95.0f + 5.0f;
        float mc = powf(m1 * m2, 0.6f) / powf(m1 + m2, 0.2f);
        float fisco = 220.0f / (m1 + m2);
        float dist = pi[2] * 2950.0f + 50.0f;
        g_pjA[gid] = make_float4(pi[5], pi[3], pi[4], mc);
        g_pjB[gid] = make_float4(fisco, dist, pi[7], 0.0f);
    }

    const float ISQ2 = 0.70710678118654752f;
    // centered iw1 dup-pairs
    if (gid >= 2048 && gid < 2176) {
        int x = gid - 2048;                       // 0..127
        int f = x & 7;
        float cm = 0.f;
        #pragma unroll
        for (int kk = 0; kk < 16; kk++) cm += iw1[kk * 8 + f];
        cm *= 0.0625f;
        ((u64*)g_all.w2)[x] = dupf(iw1[x] - cm);
    } else if (gid >= 2176 && gid < 2240) {
        int x = gid - 2176;                       // 0..63
        int k = x >> 2, s = x & 3;
        float v;
        if (s == 0) {
            float bm = 0.f;
            #pragma unroll
            for (int kk = 0; kk < 16; kk++) bm += ib1[kk];
            v = ib1[k] - bm * 0.0625f;
        } else if (s == 1) v = ig1[k] * ISQ2;
        else if (s == 2)   v = ibt1[k] * ISQ2;
        else               v = iw2[k] * ISQ2;
        ((u64*)g_all.kp2)[x] = dupf(v);
    }
}

// exact-precision gelu for the cold overlap-net path
__device__ __forceinline__ float gelu_erf(float x) {
    return 0.5f * x * (1.0f + erff(x * 0.70710678118654752f));
}

__device__ __forceinline__ void pair_features(float4 aI, float4 bI,
                                              float4 aJ, float4 bJ,
                                              float f[8]) {
    float dt   = fabsf(aI.x - aJ.x);
    float dra  = fabsf(aI.y - aJ.y);
    float ddec = fabsf(aI.z - aJ.z);
    float sky  = sqrtf(dra * dra + ddec * ddec);
    float msim = __fdividef(1.0f, 1.0f + fabsf(aI.w - aJ.w) * (1.0f / 30.0f));
    float fov  = __expf(-fabsf(bI.x - bJ.x) * 0.01f);
    float drat = __fdividef(fminf(bI.y, bJ.y), fmaxf(bI.y, bJ.y));
    float dpsi = fabsf(bI.z - bJ.z);
    f[0] = dt;  f[1] = sky;  f[2] = msim; f[3] = fov;
    f[4] = drat; f[5] = dpsi; f[6] = dra; f[7] = ddec;
}

// ---------------- Kernel 1: exp(pair logits), f32x2 dual-pair pipeline ----------------
__global__ __launch_bounds__(256, 2)
void logits_kernel() {
    int b = blockIdx.x;
    // decode (ti, tj), ti <= tj
    int ti = (int)((2.0f * NT + 1.0f -
                    sqrtf((2.0f * NT + 1.0f) * (2.0f * NT + 1.0f) - 8.0f * (float)b)) * 0.5f);
    if (ti < 0) ti = 0;
    if (ti > NT - 1) ti = NT - 1;
    while ((ti + 1) * NT - ((ti + 1) * ti) / 2 <= b) ti++;
    while (ti * NT - (ti * (ti - 1)) / 2 > b) ti--;
    int tj = ti + (b - (ti * NT - (ti * (ti - 1)) / 2));
    bool diag = (ti == tj);

    __shared__ float4 sAi[TILE], sBi[TILE], sAj[TILE], sBj[TILE];
    __shared__ float  sTile[TILE * 65];     // padded: conflict-free both orientations
    int tid = threadIdx.x;
    if (tid < TILE)            sAi[tid]            = g_pjA[ti * TILE + tid];
    else if (tid < 2 * TILE)   sBi[tid - TILE]     = g_pjB[ti * TILE + tid - TILE];
    else if (tid < 3 * TILE)   sAj[tid - 2 * TILE] = g_pjA[tj * TILE + tid - 2 * TILE];
    else                       sBj[tid - 3 * TILE] = g_pjB[tj * TILE + tid - 3 * TILE];
    if (diag && tid < TILE) sTile[tid * 65 + tid] = 0.0f;   // zero diagonal
    __syncthreads();

    int lj  = tid & (TILE - 1);
    int li0 = tid >> 6;            // 0..3
    float4 aJ = sAj[lj];
    float4 bJ = sBj[lj];
    int jcol = tj * TILE + lj;
    int ibase = ti * TILE;
    int tjbase = tj * TILE;

    // packed constants (A&S 7.1.25: |erf err| <= 2.5e-5)
    const u64 c_one  = pk2(1.0f, 1.0f);
    const u64 c_p    = pk2(0.47047f, 0.47047f);
    const u64 c_a1   = pk2(0.3480242f, 0.3480242f);
    const u64 c_a2   = pk2(-0.0958798f, -0.0958798f);
    const u64 c_a3   = pk2(0.7478556f, 0.7478556f);
    const u64 c_nl2e = pk2(-1.4426950408889634f, -1.4426950408889634f);
    const u64 c_s16  = pk2(0.0625f, 0.0625f);
    const u64 c_eps  = pk2(1e-5f, 1e-5f);
    float b2s = C_IB2;
    const u64 c_b2   = pk2(b2s, b2s);

    for (int li = li0; li < 32; li += 4) {
        int la = li, lb = li + 32;   // two independent pairs

        float fa[8], fb[8];
        pair_features(sAi[la], sBi[la], aJ, bJ, fa);
        pair_features(sAi[lb], sBi[lb], aJ, bJ, fb);

        u64 f2[8];
        #pragma unroll
        for (int q = 0; q < 8; q++) f2[q] = pk2(fa[q], fb[q]);

        // centered 8->16 matvec (h' = h - mu built in) + sum of squares
        u64 h2[16];
        u64 ss2 = 0;
        #pragma unroll
        for (int k = 0; k < 16; k++) {
            ulonglong2 p0 = c_all.w2[4 * k];
            ulonglong2 p1 = c_all.w2[4 * k + 1];
            ulonglong2 p2 = c_all.w2[4 * k + 2];
            ulonglong2 p3 = c_all.w2[4 * k + 3];
            u64 a = c_all.kp2[2 * k].x;           // centered bias
            a = fma2(p0.x, f2[0], a);
            a = fma2(p0.y, f2[1], a);
            a = fma2(p1.x, f2[2], a);
            a = fma2(p1.y, f2[3], a);
            a = fma2(p2.x, f2[4], a);
            a = fma2(p2.y, f2[5], a);
            a = fma2(p3.x, f2[6], a);
            a = fma2(p3.y, f2[7], a);
            h2[k] = a;
            ss2 = fma2(a, a, ss2);
        }

        // var = mean(h'^2); inv = rsqrt(var + eps)
        u64 var2 = fma2(ss2, c_s16, c_eps);
        float vlo, vhi; upk2(var2, vlo, vhi);
        u64 inv2 = pk2(frsq(vlo), frsq(vhi));

        // gelu(A&S 7.1.25, sqrt2 pre-folded) + logit accumulation
        u64 logit2 = c_b2;
        #pragma unroll
        for (int k = 0; k < 16; k++) {
            ulonglong2 q0 = c_all.kp2[2 * k];       // {bias, g/sqrt2}
            ulonglong2 q1 = c_all.kp2[2 * k + 1];   // {beta/sqrt2, iw2*sqrt2/2}
            u64 z = fma2(mul2(h2[k], inv2), q0.y, q1.x);   // z = xn / sqrt2

            u64 sgn = z & SGN2;
            u64 ax  = z & ABS2;
            u64 den = fma2(ax, c_p, c_one);
            float dlo, dhi; upk2(den, dlo, dhi);
            u64 tr = pk2(frcp(dlo), frcp(dhi));
            u64 poly = fma2(tr, c_a3, c_a2);
            poly = fma2(tr, poly, c_a1);
            poly = mul2(tr, poly);
            u64 mm = mul2(mul2(ax, c_nl2e), ax);
            float mlo, mhi; upk2(mm, mlo, mhi);
            u64 e = pk2(fex2(mlo), fex2(mhi));
            u64 er = fma2(poly ^ SGN2, e, c_one);   // erf(|z|) in [0,1)
            er |= sgn;                               // copysign
            // term = c_k * z * (1 + er)
            u64 zc = mul2(z, q1.y);
            logit2 = add2(logit2, zc);
            logit2 = fma2(zc, er, logit2);
        }

        float la_l, lb_l; upk2(logit2, la_l, lb_l);
        float pa = __expf(la_l);
        float pb = __expf(lb_l);

        if (!diag) {
            // direct row-orientation store (coalesced) + stage for transposed write
            g_P[(ibase + la) * NS + jcol] = pa;
            g_P[(ibase + lb) * NS + jcol] = pb;
            sTile[la * 65 + lj] = pa;
            sTile[lb * 65 + lj] = pb;
        } else {
            // stage valid entries + mirror; transposed write covers whole block
            if (la < lj) { sTile[la * 65 + lj] = pa; sTile[lj * 65 + la] = pa; }
            if (lb < lj) { sTile[lb * 65 + lj] = pb; sTile[lj * 65 + lb] = pb; }
        }
    }

    __syncthreads();
    // transposed block write: g_P[tj rows][ti cols], coalesced, conflict-free LDS
    #pragma unroll
    for (int idx = tid; idx < TILE * TILE; idx += 256) {
        int r = idx & (TILE - 1);   // consecutive within warp
        int c = idx >> 6;
        g_P[(tjbase + c) * NS + ibase + r] = sTile[r * 65 + c];
    }
}

// ------- Kernel 2: row normalization + weighted features + overlap net -------
__global__ __launch_bounds__(256)
void softmax_kernel(float* __restrict__ out) {
    int i = blockIdx.x;
    int tid = threadIdx.x;
    int lane = tid & 31, wid = tid >> 5;
    unsigned full = 0xffffffffu;

    float4 aI = g_pjA[i], bI = g_pjB[i];

    float d = 0.f;
    float a0 = 0.f, a1 = 0.f, a2 = 0.f, a3 = 0.f, a4 = 0.f, a5 = 0.f, a6 = 0.f, a7 = 0.f;
    const float* __restrict__ Prow = g_P + (size_t)i * NS;
    for (int j = tid; j < NS; j += 256) {
        float p = Prow[j];                 // exp(logit), 0 on diagonal
        float f[8];
        pair_features(aI, bI, g_pjA[j], g_pjB[j], f);
        d += p;
        a0 = fmaf(p, f[0], a0); a1 = fmaf(p, f[1], a1);
        a2 = fmaf(p, f[2], a2); a3 = fmaf(p, f[3], a3);
        a4 = fmaf(p, f[4], a4); a5 = fmaf(p, f[5], a5);
        a6 = fmaf(p, f[6], a6); a7 = fmaf(p, f[7], a7);
    }

    #pragma unroll
    for (int o = 16; o; o >>= 1) {
        d  += __shfl_xor_sync(full, d, o);
        a0 += __shfl_xor_sync(full, a0, o);
        a1 += __shfl_xor_sync(full, a1, o);
        a2 += __shfl_xor_sync(full, a2, o);
        a3 += __shfl_xor_sync(full, a3, o);
        a4 += __shfl_xor_sync(full, a4, o);
        a5 += __shfl_xor_sync(full, a5, o);
        a6 += __shfl_xor_sync(full, a6, o);
        a7 += __shfl_xor_sync(full, a7, o);
    }
    __shared__ float s_red[8][9];
    if (lane == 0) {
        s_red[wid][0] = a0; s_red[wid][1] = a1; s_red[wid][2] = a2; s_red[wid][3] = a3;
        s_red[wid][4] = a4; s_red[wid][5] = a5; s_red[wid][6] = a6; s_red[wid][7] = a7;
        s_red[wid][8] = d;
    }
    __syncthreads();
    __shared__ float s_fin[9];
    if (tid < 9) {
        float v = 0.f;
        #pragma unroll
        for (int w = 0; w < 8; w++) v += s_red[w][tid];
        s_fin[tid] = v;
    }
    __syncthreads();
    __shared__ float s_wf[8];
    if (tid < 8) s_wf[tid] = __fdividef(s_fin[tid], s_fin[8]);
    __syncthreads();

    __shared__ float s_h2[32];
    if (tid < 32) {
        float a = C_OB1(tid);
        #pragma unroll
        for (int f = 0; f < 8; f++) a = fmaf(C_OW1(tid, f), s_wf[f], a);
        float sv = a, sq = a * a;
        #pragma unroll
        for (int o = 16; o; o >>= 1) {
            sv += __shfl_xor_sync(full, sv, o);
            sq += __shfl_xor_sync(full, sq, o);
        }
        float mu  = sv * (1.0f / 32.0f);
        float var = fmaf(sq, 1.0f / 32.0f, -mu * mu);
        float inv = rsqrtf(var + 1e-5f);
        float xn  = fmaf((a - mu) * inv, C_OG1(tid), C_OBT1(tid));
        s_h2[tid] = gelu_erf(xn);
    }
    __syncthreads();
    if (tid < 16) {
        float a = C_OB2(tid);
        #pragma unroll
        for (int o = 0; o < 32; o++) a = fmaf(C_OW2(tid, o), s_h2[o], a);
        out[i * 16 + tid] = a;
    }
}

extern "C" void kernel_launch(void* const* d_in, const int* in_sizes, int n_in,
                              void* d_out, int out_size) {
    const float* params = (const float*)d_in[0];
    float* out = (float*)d_out;

    setup_kernel<<<16, 256>>>(params,
        (const float*)d_in[1], (const float*)d_in[2], (const float*)d_in[3],
        (const float*)d_in[4], (const float*)d_in[5], (const float*)d_in[6],
        (const float*)d_in[7], (const float*)d_in[8], (const float*)d_in[9],
        (const float*)d_in[10], (const float*)d_in[11], (const float*)d_in[12]);

    static void* wp = nullptr;
    if (!wp) cudaGetSymbolAddress(&wp, g_all);
    cudaMemcpyToSymbolAsync(c_all, wp, sizeof(CPack), 0, cudaMemcpyDeviceToDevice);

    logits_kernel<<<NTRI, 256>>>();
    softmax_kernel<<<NS, 256>>>(out);
}